// round 1
// baseline (speedup 1.0000x reference)
#include <cuda_runtime.h>
#include <math.h>

#define EPS 1e-5f

// ---------------- scratch (no allocations allowed) ----------------
__device__ float g_ef1[16 * 64 * 64 * 64];   // edge features after conv1
__device__ float g_ef2[16 * 64 * 64 * 64];   // edge features after conv2 (ef)
__device__ float g_xpool[16 * 256];
__device__ float g_epool[16 * 64];
__device__ float g_h[16 * 128];
__device__ float g_gate[16 * 256];

// ---------------- conv3x3 + BN + ReLU ----------------
// Block = one output row (b, h): 64 out-channels x 64 w positions.
// Thread (tx,ty): 4 w x 4 oc register tile. Channel chunks of 8 staged in smem.
template<int CIN>
__global__ __launch_bounds__(256)
void conv3x3_bn_relu(const float* __restrict__ x_in,
                     const float* __restrict__ w,
                     const float* __restrict__ bias,
                     const float* __restrict__ bng, const float* __restrict__ bnb,
                     const float* __restrict__ bnm, const float* __restrict__ bnv)
{
    constexpr int CK = 8;
    __shared__ float s_w[64 * CK * 9];        // [(oc*CK+cc)*9 + k]
    __shared__ float s_in[CK * 3 * 72];       // [(cc*3+dy)*72 + wi], wi 0..65 (w=-1..64)

    const int tid = threadIdx.x;
    const int h = blockIdx.x;
    const int b = blockIdx.y;
    const int tx = tid & 15, ty = tid >> 4;
    const int w0 = tx * 4, oc0 = ty * 4;

    const float* src = (CIN == 256) ? x_in : g_ef1;
    float* dst = (CIN == 256) ? g_ef1 : g_ef2;

    float acc[4][4] = {};

    for (int c0 = 0; c0 < CIN; c0 += CK) {
        __syncthreads();
        // stage weights for this channel chunk
        for (int i = tid; i < 64 * CK * 9; i += 256) {
            int oc = i / (CK * 9);
            int r  = i - oc * (CK * 9);
            int cc = r / 9;
            int k  = r - cc * 9;
            s_w[i] = w[(oc * CIN + c0 + cc) * 9 + k];
        }
        // stage 3 input rows per channel (with zero padding)
        for (int i = tid; i < CK * 3 * 66; i += 256) {
            int cc = i / 198;
            int r  = i - cc * 198;
            int dy = r / 66;
            int wi = r - dy * 66;
            int hin = h + dy - 1;
            int win = wi - 1;
            float v = 0.f;
            if (hin >= 0 && hin < 64 && win >= 0 && win < 64)
                v = src[(((size_t)b * CIN + c0 + cc) * 64 + hin) * 64 + win];
            s_in[(cc * 3 + dy) * 72 + wi] = v;
        }
        __syncthreads();

        for (int cc = 0; cc < CK; ++cc) {
            #pragma unroll
            for (int dy = 0; dy < 3; ++dy) {
                const float* row = &s_in[(cc * 3 + dy) * 72];
                float rv[6];
                #pragma unroll
                for (int j = 0; j < 6; ++j) rv[j] = row[w0 + j];
                #pragma unroll
                for (int dx = 0; dx < 3; ++dx) {
                    #pragma unroll
                    for (int i = 0; i < 4; ++i) {
                        float bw = s_w[((oc0 + i) * CK + cc) * 9 + dy * 3 + dx];
                        #pragma unroll
                        for (int j = 0; j < 4; ++j)
                            acc[i][j] = fmaf(bw, rv[j + dx], acc[i][j]);
                    }
                }
            }
        }
    }

    // epilogue: bias + BN + ReLU, vectorized store
    #pragma unroll
    for (int i = 0; i < 4; ++i) {
        int oc = oc0 + i;
        float inv = bng[oc] * rsqrtf(bnv[oc] + EPS);
        float sh  = bnb[oc] - bnm[oc] * inv + bias[oc] * inv;
        float4 o;
        o.x = fmaxf(acc[i][0] * inv + sh, 0.f);
        o.y = fmaxf(acc[i][1] * inv + sh, 0.f);
        o.z = fmaxf(acc[i][2] * inv + sh, 0.f);
        o.w = fmaxf(acc[i][3] * inv + sh, 0.f);
        *(float4*)&dst[(((size_t)b * 64 + oc) * 64 + h) * 64 + w0] = o;
    }
}

// ---------------- deterministic mean-pool over 64x64 ----------------
__global__ __launch_bounds__(256)
void pool_x(const float* __restrict__ x)
{
    int bc = blockIdx.x;   // b*256 + c
    const float* p = x + (size_t)bc * 4096;
    float s = 0.f;
    for (int i = threadIdx.x; i < 4096; i += 256) s += p[i];
    __shared__ float red[256];
    red[threadIdx.x] = s; __syncthreads();
    for (int st = 128; st > 0; st >>= 1) {
        if (threadIdx.x < st) red[threadIdx.x] += red[threadIdx.x + st];
        __syncthreads();
    }
    if (threadIdx.x == 0) g_xpool[bc] = red[0] * (1.f / 4096.f);
}

__global__ __launch_bounds__(256)
void pool_e()
{
    int bc = blockIdx.x;   // b*64 + c
    const float* p = g_ef2 + (size_t)bc * 4096;
    float s = 0.f;
    for (int i = threadIdx.x; i < 4096; i += 256) s += p[i];
    __shared__ float red[256];
    red[threadIdx.x] = s; __syncthreads();
    for (int st = 128; st > 0; st >>= 1) {
        if (threadIdx.x < st) red[threadIdx.x] += red[threadIdx.x + st];
        __syncthreads();
    }
    if (threadIdx.x == 0) g_epool[bc] = red[0] * (1.f / 4096.f);
}

// ---------------- gate MLP layer 1 + BN + ReLU ----------------
__global__ __launch_bounds__(128)
void gate_h(const float* __restrict__ g1_w, const float* __restrict__ g1_b,
            const float* __restrict__ gbng, const float* __restrict__ gbnb,
            const float* __restrict__ gbnm, const float* __restrict__ gbnv)
{
    int b = blockIdx.x;
    int t = threadIdx.x;   // 0..127
    __shared__ float gv[320];
    for (int i = t; i < 320; i += 128)
        gv[i] = (i < 256) ? g_xpool[b * 256 + i] : g_epool[b * 64 + (i - 256)];
    __syncthreads();
    float s = g1_b[t];
    const float* wrow = g1_w + t * 320;
    #pragma unroll 4
    for (int k = 0; k < 320; ++k) s = fmaf(gv[k], wrow[k], s);
    float inv = gbng[t] * rsqrtf(gbnv[t] + EPS);
    s = (s - gbnm[t]) * inv + gbnb[t];
    g_h[b * 128 + t] = fmaxf(s, 0.f);
}

// ---------------- gate MLP layer 2 + sigmoid ----------------
__global__ __launch_bounds__(256)
void gate_out(const float* __restrict__ g2_w, const float* __restrict__ g2_b)
{
    int b = blockIdx.x;
    int t = threadIdx.x;   // 0..255
    __shared__ float hv[128];
    if (t < 128) hv[t] = g_h[b * 128 + t];
    __syncthreads();
    float s = g2_b[t];
    const float* wrow = g2_w + t * 128;
    #pragma unroll 4
    for (int k = 0; k < 128; ++k) s = fmaf(hv[k], wrow[k], s);
    g_gate[b * 256 + t] = 1.f / (1.f + expf(-s));
}

// ---------------- 1x1 conv (64->256) + gated residual add ----------------
// Block = one output row (b, h): 256 oc x 64 w, in 4 oc-groups of 64.
__global__ __launch_bounds__(256)
void out_kernel(const float* __restrict__ x, const float* __restrict__ out_w,
                const float* __restrict__ out_b, float* __restrict__ out)
{
    __shared__ float s_ef[64 * 64];   // [c][w]
    __shared__ float s_w[64 * 64];    // [oc_local][c]
    const int tid = threadIdx.x;
    const int h = blockIdx.x;
    const int b = blockIdx.y;
    const int tx = tid & 15, ty = tid >> 4;
    const int w0 = tx * 4;

    for (int i = tid; i < 4096; i += 256) {
        int c = i >> 6, ww = i & 63;
        s_ef[i] = g_ef2[(((size_t)b * 64 + c) * 64 + h) * 64 + ww];
    }

    for (int g = 0; g < 4; ++g) {
        __syncthreads();
        for (int i = tid; i < 4096; i += 256) s_w[i] = out_w[g * 4096 + i];
        __syncthreads();

        float acc[4][4] = {};
        for (int c = 0; c < 64; ++c) {
            float4 r4 = *(const float4*)&s_ef[c * 64 + w0];
            float a0 = r4.x, a1 = r4.y, a2 = r4.z, a3 = r4.w;
            #pragma unroll
            for (int i = 0; i < 4; ++i) {
                float bw = s_w[(ty * 4 + i) * 64 + c];
                acc[i][0] = fmaf(bw, a0, acc[i][0]);
                acc[i][1] = fmaf(bw, a1, acc[i][1]);
                acc[i][2] = fmaf(bw, a2, acc[i][2]);
                acc[i][3] = fmaf(bw, a3, acc[i][3]);
            }
        }

        #pragma unroll
        for (int i = 0; i < 4; ++i) {
            int oc = g * 64 + ty * 4 + i;
            float gt = g_gate[b * 256 + oc];
            float bia = out_b[oc];
            size_t base = (((size_t)b * 256 + oc) * 64 + h) * 64 + w0;
            float4 xv = *(const float4*)&x[base];
            float4 o;
            o.x = xv.x + gt * (acc[i][0] + bia);
            o.y = xv.y + gt * (acc[i][1] + bia);
            o.z = xv.z + gt * (acc[i][2] + bia);
            o.w = xv.w + gt * (acc[i][3] + bia);
            *(float4*)&out[base] = o;
        }
    }
}

// ---------------- launch ----------------
extern "C" void kernel_launch(void* const* d_in, const int* in_sizes, int n_in,
                              void* d_out, int out_size)
{
    const float* x     = (const float*)d_in[0];
    const float* ec1_w = (const float*)d_in[1];
    const float* ec1_b = (const float*)d_in[2];
    const float* bn1_g = (const float*)d_in[3];
    const float* bn1_b = (const float*)d_in[4];
    const float* bn1_m = (const float*)d_in[5];
    const float* bn1_v = (const float*)d_in[6];
    const float* ec2_w = (const float*)d_in[7];
    const float* ec2_b = (const float*)d_in[8];
    const float* bn2_g = (const float*)d_in[9];
    const float* bn2_b = (const float*)d_in[10];
    const float* bn2_m = (const float*)d_in[11];
    const float* bn2_v = (const float*)d_in[12];
    const float* g1_w  = (const float*)d_in[13];
    const float* g1_b  = (const float*)d_in[14];
    const float* gbn_g = (const float*)d_in[15];
    const float* gbn_b = (const float*)d_in[16];
    const float* gbn_m = (const float*)d_in[17];
    const float* gbn_v = (const float*)d_in[18];
    const float* g2_w  = (const float*)d_in[19];
    const float* g2_b  = (const float*)d_in[20];
    const float* out_w = (const float*)d_in[21];
    const float* out_b = (const float*)d_in[22];
    float* out = (float*)d_out;

    dim3 grid_row(64, 16);

    conv3x3_bn_relu<256><<<grid_row, 256>>>(x, ec1_w, ec1_b, bn1_g, bn1_b, bn1_m, bn1_v);
    conv3x3_bn_relu<64><<<grid_row, 256>>>(x, ec2_w, ec2_b, bn2_g, bn2_b, bn2_m, bn2_v);
    pool_x<<<16 * 256, 256>>>(x);
    pool_e<<<16 * 64, 256>>>();
    gate_h<<<16, 128>>>(g1_w, g1_b, gbn_g, gbn_b, gbn_m, gbn_v);
    gate_out<<<16, 256>>>(g2_w, g2_b);
    out_kernel<<<grid_row, 256>>>(x, out_w, out_b, out);
}

// round 5
// speedup vs baseline: 2.9388x; 2.9388x over previous
#include <cuda_runtime.h>
#include <cuda_fp16.h>
#include <math.h>
#include <stdint.h>

#define EPS 1e-5f

// ---------------- scratch (no allocations allowed; zero-initialized at load) ----------------
__device__ __half g_xp [16u * 66 * 66 * 256];  // x padded NHWC fp16 (borders stay zero)
__device__ __half g_xp2[16u * 66 * 66 * 64];   // ef1 padded NHWC fp16 (borders stay zero)
__device__ __half g_w1p[36 * 64 * 64];         // conv1 weights [kc][oc][ch]
__device__ __half g_w2p[9 * 64 * 64];          // conv2 weights [tap][oc][ch]
__device__ float  g_ef2[16u * 64 * 64 * 64];   // ef (fp32 NCHW) for pool/out
__device__ float  g_xpool[16 * 256];
__device__ float  g_epool[16 * 64];
__device__ float  g_h[16 * 128];
__device__ float  g_gate[16 * 256];

__device__ __forceinline__ uint32_t smem_u32(const void* p) {
    uint32_t a;
    asm("{ .reg .u64 t; cvta.to.shared.u64 t, %1; cvt.u32.u64 %0, t; }" : "=r"(a) : "l"(p));
    return a;
}

// 16B-unit XOR swizzle inside a 128B row: row stride 128B, unit u in [0,8)
__device__ __forceinline__ uint32_t swz(uint32_t row, uint32_t u) {
    return row * 128u + ((u ^ (row & 7u)) * 16u);
}

#define LDMATRIX_X4(r0, r1, r2, r3, addr) \
    asm volatile("ldmatrix.sync.aligned.m8n8.x4.shared.b16 {%0,%1,%2,%3}, [%4];" \
                 : "=r"(r0), "=r"(r1), "=r"(r2), "=r"(r3) : "r"(addr))

#define MMA_16816(c, a0, a1, a2, a3, b0, b1) \
    asm volatile("mma.sync.aligned.m16n8k16.row.col.f32.f16.f16.f32 " \
                 "{%0,%1,%2,%3}, {%4,%5,%6,%7}, {%8,%9}, {%0,%1,%2,%3};" \
                 : "+f"((c)[0]), "+f"((c)[1]), "+f"((c)[2]), "+f"((c)[3]) \
                 : "r"(a0), "r"(a1), "r"(a2), "r"(a3), "r"(b0), "r"(b1))

// ---------------- pre-pass: x (fp32 NCHW) -> padded NHWC fp16 ----------------
__global__ __launch_bounds__(256)
void convert_x(const float* __restrict__ x)
{
    const int h = blockIdx.x, b = blockIdx.y, tid = threadIdx.x;
    __shared__ float t[64][65];
    for (int c0 = 0; c0 < 256; c0 += 64) {
        __syncthreads();
        for (int i = tid; i < 4096; i += 256) {
            int c = i >> 6, w = i & 63;
            t[c][w] = x[(((size_t)b * 256 + c0 + c) * 64 + h) * 64 + w];
        }
        __syncthreads();
        for (int i = tid; i < 4096; i += 256) {
            int w = i >> 6, c = i & 63;
            g_xp[((b * 66u + h + 1) * 66u + (w + 1)) * 256 + c0 + c] = __float2half_rn(t[c][w]);
        }
    }
}

// ---------------- pre-pass: weight reorder ----------------
__global__ __launch_bounds__(256)
void prep_w1(const float* __restrict__ w)  // [64][256][3][3] -> g_w1p[kc=t*4+cq][oc][j]
{
    int idx = blockIdx.x * 256 + threadIdx.x;
    if (idx >= 36 * 64 * 64) return;
    int j  = idx & 63;
    int oc = (idx >> 6) & 63;
    int kc = idx >> 12;
    int t = kc >> 2, cq = kc & 3;
    int ch = cq * 64 + j, dy = t / 3, dx = t % 3;
    g_w1p[idx] = __float2half_rn(w[((oc * 256 + ch) * 3 + dy) * 3 + dx]);
}
__global__ __launch_bounds__(256)
void prep_w2(const float* __restrict__ w)  // [64][64][3][3] -> g_w2p[t][oc][j]
{
    int idx = blockIdx.x * 256 + threadIdx.x;
    if (idx >= 9 * 64 * 64) return;
    int j  = idx & 63;
    int oc = (idx >> 6) & 63;
    int t  = idx >> 12;
    g_w2p[idx] = __float2half_rn(w[(oc * 64 + j) * 9 + t]);
}

// ---------------- mma.sync conv3x3 + BN + ReLU ----------------
// Tile: M=128 (2 output rows x 64 w), N=64 oc. 4 warps, each 32 rows x 64 oc.
// K looped in chunks of 64 (one tap x 64 ch); per chunk 4 k16 MMA steps.
template<int CIN, int NCH, bool FIRST>
__global__ __launch_bounds__(128)
void conv_mma(const float* __restrict__ bias,
              const float* __restrict__ bng, const float* __restrict__ bnb,
              const float* __restrict__ bnm, const float* __restrict__ bnv)
{
    __shared__ __align__(128) __half sA[128 * 64];   // swizzled rows of 128B
    __shared__ __align__(128) __half sB[64 * 64];
    __shared__ float sScale[64], sShift[64];

    const int tid  = threadIdx.x;
    const int wid  = tid >> 5;
    const int lane = tid & 31;
    const int h0 = blockIdx.x * 2;
    const int b  = blockIdx.y;
    const int m0 = wid * 32;

    const __half* __restrict__ xin = FIRST ? g_xp : g_xp2;
    const __half* __restrict__ wp  = FIRST ? g_w1p : g_w2p;

    if (tid < 64) {
        float inv = bng[tid] * rsqrtf(bnv[tid] + EPS);
        sScale[tid] = inv;
        sShift[tid] = bnb[tid] - bnm[tid] * inv + bias[tid] * inv;
    }

    const uint32_t sAb = smem_u32(sA);
    const uint32_t sBb = smem_u32(sB);

    // ldmatrix addresses (fixed per lane; k-step adds to unit index)
    // A tile (mt): rows m0 + mt*16 + (lane&15), unit = s*2 + (lane>>4)
    // B tile (nt): rows nt*16 + (lane&15),      unit = s*2 + (lane>>4)
    const uint32_t a_row = (uint32_t)(m0 + (lane & 15));
    const uint32_t b_row = (uint32_t)(lane & 15);
    const uint32_t u_hi  = (uint32_t)(lane >> 4);

    float acc[2][8][4];
    #pragma unroll
    for (int mt = 0; mt < 2; ++mt)
        #pragma unroll
        for (int j = 0; j < 8; ++j)
            #pragma unroll
            for (int q = 0; q < 4; ++q) acc[mt][j][q] = 0.f;

    const int hh_st = tid >> 6, w_st = tid & 63;   // staging row -> spatial

    for (int kc = 0; kc < NCH; ++kc) {
        const int t   = (CIN == 256) ? (kc >> 2) : kc;
        const int ch0 = (CIN == 256) ? ((kc & 3) * 64) : 0;
        const int dy = t / 3, dx = t % 3;

        __syncthreads();
        // stage A: thread tid owns row tid (64 halves = 8 x 16B units)
        {
            const __half* src = xin + ((size_t)((b * 66 + h0 + hh_st + dy) * 66 + (w_st + dx)) * CIN + ch0);
            #pragma unroll
            for (int c = 0; c < 8; ++c)
                *(uint4*)((char*)sA + swz((uint32_t)tid, c)) = *(const uint4*)(src + c * 8);
        }
        // stage B: rows 0..63 (oc)
        if (tid < 64) {
            const __half* src = wp + ((size_t)(kc * 64 + tid) * 64);
            #pragma unroll
            for (int c = 0; c < 8; ++c)
                *(uint4*)((char*)sB + swz((uint32_t)tid, c)) = *(const uint4*)(src + c * 8);
        }
        __syncthreads();

        #pragma unroll
        for (int s = 0; s < 4; ++s) {
            const uint32_t u = (uint32_t)(s * 2) + u_hi;
            uint32_t a[2][4];
            #pragma unroll
            for (int mt = 0; mt < 2; ++mt)
                LDMATRIX_X4(a[mt][0], a[mt][1], a[mt][2], a[mt][3],
                            sAb + swz(a_row + mt * 16, u));
            uint32_t bf[4][4];
            #pragma unroll
            for (int nt = 0; nt < 4; ++nt)
                LDMATRIX_X4(bf[nt][0], bf[nt][1], bf[nt][2], bf[nt][3],
                            sBb + swz(b_row + nt * 16, u));
            #pragma unroll
            for (int mt = 0; mt < 2; ++mt)
                #pragma unroll
                for (int j = 0; j < 8; ++j) {
                    const int nt = j >> 1, lo = j & 1;
                    MMA_16816(acc[mt][j], a[mt][0], a[mt][1], a[mt][2], a[mt][3],
                              bf[nt][lo], bf[nt][2 + lo]);
                }
        }
    }

    // ---------------- epilogue: BN + ReLU ----------------
    const int r0 = lane >> 2;             // row within 8
    const int c0 = (lane & 3) * 2;        // col pair base
    #pragma unroll
    for (int mt = 0; mt < 2; ++mt) {
        #pragma unroll
        for (int half = 0; half < 2; ++half) {   // row r0 / r0+8
            const int m = m0 + mt * 16 + r0 + half * 8;
            const int hh = m >> 6, w = m & 63;
            if (FIRST) {
                __half* dst = g_xp2 + ((size_t)((b * 66 + h0 + hh + 1) * 66) + (w + 1)) * 64;
                #pragma unroll
                for (int j = 0; j < 8; ++j) {
                    const int oc = j * 8 + c0;
                    float v0 = fmaxf(acc[mt][j][half * 2]     * sScale[oc]     + sShift[oc],     0.f);
                    float v1 = fmaxf(acc[mt][j][half * 2 + 1] * sScale[oc + 1] + sShift[oc + 1], 0.f);
                    *(half2*)(dst + oc) = __floats2half2_rn(v0, v1);
                }
            } else {
                const int h = h0 + hh;
                #pragma unroll
                for (int j = 0; j < 8; ++j) {
                    const int oc = j * 8 + c0;
                    float v0 = fmaxf(acc[mt][j][half * 2]     * sScale[oc]     + sShift[oc],     0.f);
                    float v1 = fmaxf(acc[mt][j][half * 2 + 1] * sScale[oc + 1] + sShift[oc + 1], 0.f);
                    g_ef2[(((size_t)b * 64 + oc)     * 64 + h) * 64 + w] = v0;
                    g_ef2[(((size_t)b * 64 + oc + 1) * 64 + h) * 64 + w] = v1;
                }
            }
        }
    }
}

// ---------------- deterministic mean-pool (float4) ----------------
__global__ __launch_bounds__(256)
void pool_x(const float* __restrict__ x)
{
    int bc = blockIdx.x;
    const float4* p = (const float4*)(x + (size_t)bc * 4096);
    float s = 0.f;
    for (int i = threadIdx.x; i < 1024; i += 256) {
        float4 v = p[i];
        s += (v.x + v.y) + (v.z + v.w);
    }
    __shared__ float red[256];
    red[threadIdx.x] = s; __syncthreads();
    for (int st = 128; st > 0; st >>= 1) {
        if (threadIdx.x < st) red[threadIdx.x] += red[threadIdx.x + st];
        __syncthreads();
    }
    if (threadIdx.x == 0) g_xpool[bc] = red[0] * (1.f / 4096.f);
}
__global__ __launch_bounds__(256)
void pool_e()
{
    int bc = blockIdx.x;
    const float4* p = (const float4*)(g_ef2 + (size_t)bc * 4096);
    float s = 0.f;
    for (int i = threadIdx.x; i < 1024; i += 256) {
        float4 v = p[i];
        s += (v.x + v.y) + (v.z + v.w);
    }
    __shared__ float red[256];
    red[threadIdx.x] = s; __syncthreads();
    for (int st = 128; st > 0; st >>= 1) {
        if (threadIdx.x < st) red[threadIdx.x] += red[threadIdx.x + st];
        __syncthreads();
    }
    if (threadIdx.x == 0) g_epool[bc] = red[0] * (1.f / 4096.f);
}

// ---------------- gate MLP ----------------
__global__ __launch_bounds__(128)
void gate_h(const float* __restrict__ g1_w, const float* __restrict__ g1_b,
            const float* __restrict__ gbng, const float* __restrict__ gbnb,
            const float* __restrict__ gbnm, const float* __restrict__ gbnv)
{
    int b = blockIdx.x;
    int t = threadIdx.x;
    __shared__ float gv[320];
    for (int i = t; i < 320; i += 128)
        gv[i] = (i < 256) ? g_xpool[b * 256 + i] : g_epool[b * 64 + (i - 256)];
    __syncthreads();
    float s = g1_b[t];
    const float* wrow = g1_w + t * 320;
    #pragma unroll 4
    for (int k = 0; k < 320; ++k) s = fmaf(gv[k], wrow[k], s);
    float inv = gbng[t] * rsqrtf(gbnv[t] + EPS);
    s = (s - gbnm[t]) * inv + gbnb[t];
    g_h[b * 128 + t] = fmaxf(s, 0.f);
}
__global__ __launch_bounds__(256)
void gate_out(const float* __restrict__ g2_w, const float* __restrict__ g2_b)
{
    int b = blockIdx.x;
    int t = threadIdx.x;
    __shared__ float hv[128];
    if (t < 128) hv[t] = g_h[b * 128 + t];
    __syncthreads();
    float s = g2_b[t];
    const float* wrow = g2_w + t * 128;
    #pragma unroll 4
    for (int k = 0; k < 128; ++k) s = fmaf(hv[k], wrow[k], s);
    g_gate[b * 256 + t] = 1.f / (1.f + expf(-s));
}

// ---------------- 1x1 conv (64->256) + gated residual add (fp32) ----------------
__global__ __launch_bounds__(256)
void out_kernel(const float* __restrict__ x, const float* __restrict__ out_w,
                const float* __restrict__ out_b, float* __restrict__ out)
{
    __shared__ float s_ef[64 * 64];
    __shared__ float s_w[64 * 64];
    const int tid = threadIdx.x;
    const int h = blockIdx.x;
    const int b = blockIdx.y;
    const int tx = tid & 15, ty = tid >> 4;
    const int w0 = tx * 4;

    for (int i = tid; i < 4096; i += 256) {
        int c = i >> 6, ww = i & 63;
        s_ef[i] = g_ef2[(((size_t)b * 64 + c) * 64 + h) * 64 + ww];
    }

    for (int g = 0; g < 4; ++g) {
        __syncthreads();
        for (int i = tid; i < 4096; i += 256) s_w[i] = out_w[g * 4096 + i];
        __syncthreads();

        float acc[4][4] = {};
        for (int c = 0; c < 64; ++c) {
            float4 r4 = *(const float4*)&s_ef[c * 64 + w0];
            #pragma unroll
            for (int i = 0; i < 4; ++i) {
                float bw = s_w[(ty * 4 + i) * 64 + c];
                acc[i][0] = fmaf(bw, r4.x, acc[i][0]);
                acc[i][1] = fmaf(bw, r4.y, acc[i][1]);
                acc[i][2] = fmaf(bw, r4.z, acc[i][2]);
                acc[i][3] = fmaf(bw, r4.w, acc[i][3]);
            }
        }

        #pragma unroll
        for (int i = 0; i < 4; ++i) {
            int oc = g * 64 + ty * 4 + i;
            float gt = g_gate[b * 256 + oc];
            float bia = out_b[oc];
            size_t base = (((size_t)b * 256 + oc) * 64 + h) * 64 + w0;
            float4 xv = *(const float4*)&x[base];
            float4 o;
            o.x = xv.x + gt * (acc[i][0] + bia);
            o.y = xv.y + gt * (acc[i][1] + bia);
            o.z = xv.z + gt * (acc[i][2] + bia);
            o.w = xv.w + gt * (acc[i][3] + bia);
            *(float4*)&out[base] = o;
        }
    }
}

// ---------------- launch ----------------
extern "C" void kernel_launch(void* const* d_in, const int* in_sizes, int n_in,
                              void* d_out, int out_size)
{
    const float* x     = (const float*)d_in[0];
    const float* ec1_w = (const float*)d_in[1];
    const float* ec1_b = (const float*)d_in[2];
    const float* bn1_g = (const float*)d_in[3];
    const float* bn1_b = (const float*)d_in[4];
    const float* bn1_m = (const float*)d_in[5];
    const float* bn1_v = (const float*)d_in[6];
    const float* ec2_w = (const float*)d_in[7];
    const float* ec2_b = (const float*)d_in[8];
    const float* bn2_g = (const float*)d_in[9];
    const float* bn2_b = (const float*)d_in[10];
    const float* bn2_m = (const float*)d_in[11];
    const float* bn2_v = (const float*)d_in[12];
    const float* g1_w  = (const float*)d_in[13];
    const float* g1_b  = (const float*)d_in[14];
    const float* gbn_g = (const float*)d_in[15];
    const float* gbn_b = (const float*)d_in[16];
    const float* gbn_m = (const float*)d_in[17];
    const float* gbn_v = (const float*)d_in[18];
    const float* g2_w  = (const float*)d_in[19];
    const float* g2_b  = (const float*)d_in[20];
    const float* out_w = (const float*)d_in[21];
    const float* out_b = (const float*)d_in[22];
    float* out = (float*)d_out;

    convert_x<<<dim3(64, 16), 256>>>(x);
    prep_w1<<<576, 256>>>(ec1_w);
    prep_w2<<<144, 256>>>(ec2_w);

    conv_mma<256, 36, true ><<<dim3(32, 16), 128>>>(ec1_b, bn1_g, bn1_b, bn1_m, bn1_v);
    conv_mma< 64,  9, false><<<dim3(32, 16), 128>>>(ec2_b, bn2_g, bn2_b, bn2_m, bn2_v);

    pool_x<<<16 * 256, 256>>>(x);
    pool_e<<<16 * 64, 256>>>();
    gate_h<<<16, 128>>>(g1_w, g1_b, gbn_g, gbn_b, gbn_m, gbn_v);
    gate_out<<<16, 256>>>(g2_w, g2_b);
    out_kernel<<<dim3(64, 16), 256>>>(x, out_w, out_b, out);
}

// round 6
// speedup vs baseline: 5.0106x; 1.7050x over previous
#include <cuda_runtime.h>
#include <cuda_fp16.h>
#include <math.h>
#include <stdint.h>

#define EPS 1e-5f

// ---------------- scratch (no allocations allowed; zero-initialized at load) ----------------
__device__ __half g_xp [16u * 66 * 66 * 256];  // x padded NHWC fp16 (borders stay zero)
__device__ __half g_xp2[16u * 66 * 66 * 64];   // ef1 padded NHWC fp16 (borders stay zero)
__device__ __half g_ef [16u * 64 * 64 * 64];   // ef NHWC fp16 [b][h*64+w][ch]
__device__ __half g_w1p[36 * 64 * 64];         // conv1 weights [kc=t*4+cq][oc][ch]
__device__ __half g_w2p[9 * 64 * 64];          // conv2 weights [t][oc][ch]
__device__ __half g_wop[256 * 64];             // out_w fp16 [oc][ch]
__device__ float  g_xpool[16 * 256];
__device__ float  g_ep1[16 * 16 * 64];         // partial e-pool sums [b][seg][ch]
__device__ float  g_h[16 * 128];
__device__ float  g_gate[16 * 256];

__device__ __forceinline__ uint32_t smem_u32(const void* p) {
    uint32_t a;
    asm("{ .reg .u64 t; cvta.to.shared.u64 t, %1; cvt.u32.u64 %0, t; }" : "=r"(a) : "l"(p));
    return a;
}

// 16B-unit XOR swizzle inside a 128B row: row stride 128B, unit u in [0,8)
__device__ __forceinline__ uint32_t swz(uint32_t row, uint32_t u) {
    return row * 128u + ((u ^ (row & 7u)) * 16u);
}

#define LDMATRIX_X4(r0, r1, r2, r3, addr) \
    asm volatile("ldmatrix.sync.aligned.m8n8.x4.shared.b16 {%0,%1,%2,%3}, [%4];" \
                 : "=r"(r0), "=r"(r1), "=r"(r2), "=r"(r3) : "r"(addr))

#define MMA_16816(c, a0, a1, a2, a3, b0, b1) \
    asm volatile("mma.sync.aligned.m16n8k16.row.col.f32.f16.f16.f32 " \
                 "{%0,%1,%2,%3}, {%4,%5,%6,%7}, {%8,%9}, {%0,%1,%2,%3};" \
                 : "+f"((c)[0]), "+f"((c)[1]), "+f"((c)[2]), "+f"((c)[3]) \
                 : "r"(a0), "r"(a1), "r"(a2), "r"(a3), "r"(b0), "r"(b1))

// ---------------- pre-pass: x (fp32 NCHW) -> padded NHWC fp16 ----------------
__global__ __launch_bounds__(256)
void convert_x(const float* __restrict__ x)
{
    const int h = blockIdx.x, b = blockIdx.y, tid = threadIdx.x;
    __shared__ float t[64][65];
    for (int c0 = 0; c0 < 256; c0 += 64) {
        __syncthreads();
        for (int i = tid; i < 4096; i += 256) {
            int c = i >> 6, w = i & 63;
            t[c][w] = x[(((size_t)b * 256 + c0 + c) * 64 + h) * 64 + w];
        }
        __syncthreads();
        for (int i = tid; i < 4096; i += 256) {
            int w = i >> 6, c = i & 63;
            g_xp[((b * 66u + h + 1) * 66u + (w + 1)) * 256 + c0 + c] = __float2half_rn(t[c][w]);
        }
    }
}

// ---------------- pre-pass: weight reorder ----------------
__global__ __launch_bounds__(256)
void prep_w1(const float* __restrict__ w)  // [64][256][3][3] -> g_w1p[kc=t*4+cq][oc][j]
{
    int idx = blockIdx.x * 256 + threadIdx.x;
    if (idx >= 36 * 64 * 64) return;
    int j  = idx & 63;
    int oc = (idx >> 6) & 63;
    int kc = idx >> 12;
    int t = kc >> 2, cq = kc & 3;
    int ch = cq * 64 + j, dy = t / 3, dx = t % 3;
    g_w1p[idx] = __float2half_rn(w[((oc * 256 + ch) * 3 + dy) * 3 + dx]);
}
__global__ __launch_bounds__(256)
void prep_w2(const float* __restrict__ w)  // [64][64][3][3] -> g_w2p[t][oc][j]
{
    int idx = blockIdx.x * 256 + threadIdx.x;
    if (idx >= 9 * 64 * 64) return;
    int j  = idx & 63;
    int oc = (idx >> 6) & 63;
    int t  = idx >> 12;
    g_w2p[idx] = __float2half_rn(w[(oc * 64 + j) * 9 + t]);
}
__global__ __launch_bounds__(256)
void prep_wo(const float* __restrict__ w)  // [256][64] -> fp16
{
    int idx = blockIdx.x * 256 + threadIdx.x;
    if (idx < 256 * 64) g_wop[idx] = __float2half_rn(w[idx]);
}

// ---------------- mma.sync conv3x3 + BN + ReLU (A-tile staged once per ch-group) ----------------
// Tile: M=128 (2 output rows x 64 w), N=64 oc. 4 warps, each 32 rows x 64 oc.
// smem: sIn = 4 input rows x 66 w (264 spatial rows x 128B) staged once per 64-ch group;
//       sB  = double-buffered 64x64 weight chunk per tap.
template<int CIN, int NG, bool FIRST>
__global__ __launch_bounds__(128)
void conv_mma(const float* __restrict__ bias,
              const float* __restrict__ bng, const float* __restrict__ bnb,
              const float* __restrict__ bnm, const float* __restrict__ bnv)
{
    extern __shared__ __align__(128) char dsm[];
    __half* sIn  = (__half*)dsm;                    // 264*128 = 33792 B
    char*   sBm  = dsm + 264 * 128;                 // 2 * 8192 B
    float*  sScale = (float*)(dsm + 264 * 128 + 16384);
    float*  sShift = sScale + 64;

    const int tid  = threadIdx.x;
    const int wid  = tid >> 5;
    const int lane = tid & 31;
    const int h0 = blockIdx.x * 2;
    const int b  = blockIdx.y;
    const int m0 = wid * 32;

    const __half* __restrict__ xin = FIRST ? g_xp : g_xp2;
    const __half* __restrict__ wgt = FIRST ? g_w1p : g_w2p;

    if (tid < 64) {
        float inv = bng[tid] * rsqrtf(bnv[tid] + EPS);
        sScale[tid] = inv;
        sShift[tid] = bnb[tid] - bnm[tid] * inv + bias[tid] * inv;
    }

    const uint32_t sInb = smem_u32(sIn);
    const uint32_t sBb  = smem_u32(sBm);

    // per-lane spatial row base for A fragments (m -> (hh, w) -> row hh*66 + w)
    int rb[2];
    #pragma unroll
    for (int mt = 0; mt < 2; ++mt) {
        int m_r = m0 + mt * 16 + (lane & 15);
        rb[mt] = (m_r >> 6) * 66 + (m_r & 63);
    }
    const uint32_t u_hi  = (uint32_t)(lane >> 4);
    const uint32_t b_row = (uint32_t)(lane & 15);

    float acc[2][8][4];
    #pragma unroll
    for (int mt = 0; mt < 2; ++mt)
        #pragma unroll
        for (int j = 0; j < 8; ++j)
            #pragma unroll
            for (int q = 0; q < 4; ++q) acc[mt][j][q] = 0.f;

    for (int g = 0; g < NG; ++g) {
        if (g) __syncthreads();   // prior group's smem reads done
        const int ch0 = g * 64;
        // stage input tile: 264 rows x 8 units
        for (int i = tid; i < 264 * 8; i += 128) {
            int r = i >> 3, u = i & 7;
            int dyr = r / 66, wpos = r - dyr * 66;
            const __half* src = xin + ((size_t)((b * 66 + h0 + dyr) * 66 + wpos)) * CIN + ch0 + u * 8;
            *(uint4*)((char*)sIn + swz((uint32_t)r, (uint32_t)u)) = *(const uint4*)src;
        }
        // stage B for tap 0
        {
            const int kci = FIRST ? g : 0;
            const __half* ws = wgt + (size_t)kci * 4096;
            #pragma unroll
            for (int q = 0; q < 4; ++q) {
                int i = q * 128 + tid, r = i >> 3, u = i & 7;
                *(uint4*)(sBm + swz((uint32_t)r, (uint32_t)u)) = *(const uint4*)(ws + r * 64 + u * 8);
            }
        }
        __syncthreads();

        for (int t = 0; t < 9; ++t) {
            if (t) __syncthreads();
            const int cur = t & 1;
            if (t < 8) {   // prefetch next tap's B into the other buffer
                const int kci = FIRST ? ((t + 1) * 4 + g) : (t + 1);
                const __half* ws = wgt + (size_t)kci * 4096;
                char* dstb = sBm + ((t + 1) & 1) * 8192;
                #pragma unroll
                for (int q = 0; q < 4; ++q) {
                    int i = q * 128 + tid, r = i >> 3, u = i & 7;
                    *(uint4*)(dstb + swz((uint32_t)r, (uint32_t)u)) = *(const uint4*)(ws + r * 64 + u * 8);
                }
            }
            const int off = (t / 3) * 66 + (t % 3);
            const uint32_t bbase = sBb + cur * 8192;
            #pragma unroll
            for (int s = 0; s < 4; ++s) {
                const uint32_t u = (uint32_t)(s * 2) + u_hi;
                uint32_t a[2][4];
                #pragma unroll
                for (int mt = 0; mt < 2; ++mt)
                    LDMATRIX_X4(a[mt][0], a[mt][1], a[mt][2], a[mt][3],
                                sInb + swz((uint32_t)(rb[mt] + off), u));
                uint32_t bf[4][4];
                #pragma unroll
                for (int nt = 0; nt < 4; ++nt)
                    LDMATRIX_X4(bf[nt][0], bf[nt][1], bf[nt][2], bf[nt][3],
                                bbase + swz(b_row + nt * 16, u));
                #pragma unroll
                for (int mt = 0; mt < 2; ++mt)
                    #pragma unroll
                    for (int j = 0; j < 8; ++j) {
                        const int nt = j >> 1, lo = j & 1;
                        MMA_16816(acc[mt][j], a[mt][0], a[mt][1], a[mt][2], a[mt][3],
                                  bf[nt][lo], bf[nt][2 + lo]);
                    }
            }
        }
    }

    // ---------------- epilogue: BN + ReLU ----------------
    const int r0 = lane >> 2;
    const int c0 = (lane & 3) * 2;
    #pragma unroll
    for (int mt = 0; mt < 2; ++mt) {
        #pragma unroll
        for (int half = 0; half < 2; ++half) {
            const int m = m0 + mt * 16 + r0 + half * 8;
            const int hh = m >> 6, w = m & 63;
            if (FIRST) {
                __half* dst = g_xp2 + ((size_t)((b * 66 + h0 + hh + 1) * 66) + (w + 1)) * 64;
                #pragma unroll
                for (int j = 0; j < 8; ++j) {
                    const int oc = j * 8 + c0;
                    float v0 = fmaxf(acc[mt][j][half * 2]     * sScale[oc]     + sShift[oc],     0.f);
                    float v1 = fmaxf(acc[mt][j][half * 2 + 1] * sScale[oc + 1] + sShift[oc + 1], 0.f);
                    *(half2*)(dst + oc) = __floats2half2_rn(v0, v1);
                }
            } else {
                __half* dst = g_ef + ((size_t)(b * 4096 + (h0 + hh) * 64 + w)) * 64;
                #pragma unroll
                for (int j = 0; j < 8; ++j) {
                    const int oc = j * 8 + c0;
                    float v0 = fmaxf(acc[mt][j][half * 2]     * sScale[oc]     + sShift[oc],     0.f);
                    float v1 = fmaxf(acc[mt][j][half * 2 + 1] * sScale[oc + 1] + sShift[oc + 1], 0.f);
                    *(half2*)(dst + oc) = __floats2half2_rn(v0, v1);
                }
            }
        }
    }
}

// ---------------- deterministic mean-pool of x (fp32, float4) ----------------
__global__ __launch_bounds__(256)
void pool_x(const float* __restrict__ x)
{
    int bc = blockIdx.x;
    const float4* p = (const float4*)(x + (size_t)bc * 4096);
    float s = 0.f;
    for (int i = threadIdx.x; i < 1024; i += 256) {
        float4 v = p[i];
        s += (v.x + v.y) + (v.z + v.w);
    }
    __shared__ float red[256];
    red[threadIdx.x] = s; __syncthreads();
    for (int st = 128; st > 0; st >>= 1) {
        if (threadIdx.x < st) red[threadIdx.x] += red[threadIdx.x + st];
        __syncthreads();
    }
    if (threadIdx.x == 0) g_xpool[bc] = red[0] * (1.f / 4096.f);
}

// ---------------- e-pool stage 1: partial per-channel sums over 256 positions ----------------
__global__ __launch_bounds__(256)
void pool_e1()
{
    const int seg = blockIdx.x, b = blockIdx.y;
    const int ch = threadIdx.x & 63, ps = threadIdx.x >> 6;
    const __half* p = g_ef + ((size_t)(b * 4096 + seg * 256 + ps * 64)) * 64;
    float s = 0.f;
    #pragma unroll 4
    for (int k = 0; k < 64; ++k) s += __half2float(p[k * 64 + ch]);
    __shared__ float sm[256];
    sm[threadIdx.x] = s; __syncthreads();
    if (threadIdx.x < 64)
        g_ep1[(b * 16 + seg) * 64 + threadIdx.x] =
            sm[threadIdx.x] + sm[threadIdx.x + 64] + sm[threadIdx.x + 128] + sm[threadIdx.x + 192];
}

// ---------------- gate MLP (folds e-pool partials) ----------------
__global__ __launch_bounds__(128)
void gate_h(const float* __restrict__ g1_w, const float* __restrict__ g1_b,
            const float* __restrict__ gbng, const float* __restrict__ gbnb,
            const float* __restrict__ gbnm, const float* __restrict__ gbnv)
{
    int b = blockIdx.x;
    int t = threadIdx.x;
    __shared__ float gv[320];
    for (int i = t; i < 320; i += 128) {
        if (i < 256) gv[i] = g_xpool[b * 256 + i];
        else {
            int c = i - 256;
            float s = 0.f;
            #pragma unroll
            for (int seg = 0; seg < 16; ++seg) s += g_ep1[(b * 16 + seg) * 64 + c];
            gv[i] = s * (1.f / 4096.f);
        }
    }
    __syncthreads();
    float s = g1_b[t];
    const float* wrow = g1_w + t * 320;
    #pragma unroll 4
    for (int k = 0; k < 320; ++k) s = fmaf(gv[k], wrow[k], s);
    float inv = gbng[t] * rsqrtf(gbnv[t] + EPS);
    s = (s - gbnm[t]) * inv + gbnb[t];
    g_h[b * 128 + t] = fmaxf(s, 0.f);
}
__global__ __launch_bounds__(256)
void gate_out(const float* __restrict__ g2_w, const float* __restrict__ g2_b)
{
    int b = blockIdx.x;
    int t = threadIdx.x;
    __shared__ float hv[128];
    if (t < 128) hv[t] = g_h[b * 128 + t];
    __syncthreads();
    float s = g2_b[t];
    const float* wrow = g2_w + t * 128;
    #pragma unroll 4
    for (int k = 0; k < 128; ++k) s = fmaf(hv[k], wrow[k], s);
    g_gate[b * 256 + t] = 1.f / (1.f + expf(-s));
}

// ---------------- 1x1 conv (64->256) via HMMA + gated residual add ----------------
// Per (b,h): D[256 oc, 64 w] = W[256,64ch] . ef[64 w,64 ch]^T ; 8 warps, each 32 oc x 64 w.
__global__ __launch_bounds__(256)
void out_mma(const float* __restrict__ x, const float* __restrict__ out_b,
             float* __restrict__ out)
{
    __shared__ __align__(128) __half sW[256 * 64];
    __shared__ __align__(128) __half sE[64 * 64];
    const int tid = threadIdx.x, wid = tid >> 5, lane = tid & 31;
    const int h = blockIdx.x, b = blockIdx.y;

    for (int i = tid; i < 2048; i += 256) {
        int r = i >> 3, u = i & 7;
        *(uint4*)((char*)sW + swz((uint32_t)r, (uint32_t)u)) = *(const uint4*)(g_wop + r * 64 + u * 8);
    }
    for (int i = tid; i < 512; i += 256) {
        int r = i >> 3, u = i & 7;
        *(uint4*)((char*)sE + swz((uint32_t)r, (uint32_t)u)) =
            *(const uint4*)(g_ef + ((size_t)(b * 4096 + h * 64 + r)) * 64 + u * 8);
    }
    __syncthreads();

    const int m0 = wid * 32;
    const uint32_t sWb = smem_u32(sW), sEb = smem_u32(sE);
    const uint32_t a_row = (uint32_t)(m0 + (lane & 15));
    const uint32_t b_row = (uint32_t)(lane & 15);
    const uint32_t u_hi  = (uint32_t)(lane >> 4);

    float acc[2][8][4];
    #pragma unroll
    for (int mt = 0; mt < 2; ++mt)
        #pragma unroll
        for (int j = 0; j < 8; ++j)
            #pragma unroll
            for (int q = 0; q < 4; ++q) acc[mt][j][q] = 0.f;

    #pragma unroll
    for (int s = 0; s < 4; ++s) {
        const uint32_t u = (uint32_t)(s * 2) + u_hi;
        uint32_t a[2][4];
        #pragma unroll
        for (int mt = 0; mt < 2; ++mt)
            LDMATRIX_X4(a[mt][0], a[mt][1], a[mt][2], a[mt][3], sWb + swz(a_row + mt * 16, u));
        uint32_t bf[4][4];
        #pragma unroll
        for (int nt = 0; nt < 4; ++nt)
            LDMATRIX_X4(bf[nt][0], bf[nt][1], bf[nt][2], bf[nt][3], sEb + swz(b_row + nt * 16, u));
        #pragma unroll
        for (int mt = 0; mt < 2; ++mt)
            #pragma unroll
            for (int j = 0; j < 8; ++j) {
                const int nt = j >> 1, lo = j & 1;
                MMA_16816(acc[mt][j], a[mt][0], a[mt][1], a[mt][2], a[mt][3],
                          bf[nt][lo], bf[nt][2 + lo]);
            }
    }

    const int r0 = lane >> 2, c0 = (lane & 3) * 2;
    #pragma unroll
    for (int mt = 0; mt < 2; ++mt) {
        #pragma unroll
        for (int half = 0; half < 2; ++half) {
            const int oc = m0 + mt * 16 + r0 + half * 8;
            const float gt = g_gate[b * 256 + oc];
            const float bia = out_b[oc];
            const size_t base = ((size_t)(b * 256 + oc) * 64 + h) * 64;
            #pragma unroll
            for (int j = 0; j < 8; ++j) {
                const int w = j * 8 + c0;
                float2 xv = *(const float2*)&x[base + w];
                float2 o;
                o.x = xv.x + gt * (acc[mt][j][half * 2]     + bia);
                o.y = xv.y + gt * (acc[mt][j][half * 2 + 1] + bia);
                *(float2*)&out[base + w] = o;
            }
        }
    }
}

// ---------------- launch ----------------
extern "C" void kernel_launch(void* const* d_in, const int* in_sizes, int n_in,
                              void* d_out, int out_size)
{
    const float* x     = (const float*)d_in[0];
    const float* ec1_w = (const float*)d_in[1];
    const float* ec1_b = (const float*)d_in[2];
    const float* bn1_g = (const float*)d_in[3];
    const float* bn1_b = (const float*)d_in[4];
    const float* bn1_m = (const float*)d_in[5];
    const float* bn1_v = (const float*)d_in[6];
    const float* ec2_w = (const float*)d_in[7];
    const float* ec2_b = (const float*)d_in[8];
    const float* bn2_g = (const float*)d_in[9];
    const float* bn2_b = (const float*)d_in[10];
    const float* bn2_m = (const float*)d_in[11];
    const float* bn2_v = (const float*)d_in[12];
    const float* g1_w  = (const float*)d_in[13];
    const float* g1_b  = (const float*)d_in[14];
    const float* gbn_g = (const float*)d_in[15];
    const float* gbn_b = (const float*)d_in[16];
    const float* gbn_m = (const float*)d_in[17];
    const float* gbn_v = (const float*)d_in[18];
    const float* g2_w  = (const float*)d_in[19];
    const float* g2_b  = (const float*)d_in[20];
    const float* out_w = (const float*)d_in[21];
    const float* out_b = (const float*)d_in[22];
    float* out = (float*)d_out;

    const int CONV_SMEM = 264 * 128 + 2 * 8192 + 2 * 64 * (int)sizeof(float);  // 50688
    cudaFuncSetAttribute(conv_mma<256, 4, true >, cudaFuncAttributeMaxDynamicSharedMemorySize, CONV_SMEM);
    cudaFuncSetAttribute(conv_mma< 64, 1, false>, cudaFuncAttributeMaxDynamicSharedMemorySize, CONV_SMEM);

    convert_x<<<dim3(64, 16), 256>>>(x);
    prep_w1<<<576, 256>>>(ec1_w);
    prep_w2<<<144, 256>>>(ec2_w);
    prep_wo<<<64, 256>>>(out_w);

    conv_mma<256, 4, true ><<<dim3(32, 16), 128, CONV_SMEM>>>(ec1_b, bn1_g, bn1_b, bn1_m, bn1_v);
    conv_mma< 64, 1, false><<<dim3(32, 16), 128, CONV_SMEM>>>(ec2_b, bn2_g, bn2_b, bn2_m, bn2_v);

    pool_x<<<16 * 256, 256>>>(x);
    pool_e1<<<dim3(16, 16), 256>>>();
    gate_h<<<16, 128>>>(g1_w, g1_b, gbn_g, gbn_b, gbn_m, gbn_v);
    gate_out<<<16, 256>>>(g2_w, g2_b);
    out_mma<<<dim3(64, 16), 256>>>(x, out_b, out);
}

// round 9
// speedup vs baseline: 5.7302x; 1.1436x over previous
#include <cuda_runtime.h>
#include <cuda_fp16.h>
#include <math.h>
#include <stdint.h>

#define EPS 1e-5f

// ---------------- scratch (no allocations allowed; zero-initialized at load) ----------------
__device__ __half g_xp [16u * 66 * 66 * 256];  // x padded NHWC fp16 (borders stay zero)
__device__ __half g_xp2[16u * 66 * 66 * 64];   // ef1 padded NHWC fp16 (borders stay zero)
__device__ __half g_ef [16u * 64 * 64 * 64];   // ef NHWC fp16 [b][h*64+w][ch]
__device__ __half g_w1p[36 * 64 * 64];         // conv1 weights [kc=t*4+cq][oc][ch]
__device__ __half g_w2p[9 * 64 * 64];          // conv2 weights [t][oc][ch]
__device__ __half g_wop[256 * 64];             // out_w fp16 [oc][ch]
__device__ float  g_xph[16 * 64 * 256];        // per-(b,h) channel sums of x
__device__ float  g_ep1[16 * 32 * 64];         // partial e-pool sums [b][tile][ch]
__device__ float  g_gate[16 * 256];

__device__ __forceinline__ uint32_t smem_u32(const void* p) {
    uint32_t a;
    asm("{ .reg .u64 t; cvta.to.shared.u64 t, %1; cvt.u32.u64 %0, t; }" : "=r"(a) : "l"(p));
    return a;
}

// 16B-unit XOR swizzle inside a 128B row: row stride 128B, unit u in [0,8)
__device__ __forceinline__ uint32_t swz(uint32_t row, uint32_t u) {
    return row * 128u + ((u ^ (row & 7u)) * 16u);
}

#define CP_ASYNC16(dst, src) \
    asm volatile("cp.async.cg.shared.global [%0], [%1], 16;" :: "r"(dst), "l"(src))
#define CP_COMMIT() asm volatile("cp.async.commit_group;" ::: "memory")
#define CP_WAIT0()  asm volatile("cp.async.wait_group 0;" ::: "memory")

#define LDMATRIX_X4(r0, r1, r2, r3, addr) \
    asm volatile("ldmatrix.sync.aligned.m8n8.x4.shared.b16 {%0,%1,%2,%3}, [%4];" \
                 : "=r"(r0), "=r"(r1), "=r"(r2), "=r"(r3) : "r"(addr))

#define MMA_16816(c, a0, a1, a2, a3, b0, b1) \
    asm volatile("mma.sync.aligned.m16n8k16.row.col.f32.f16.f16.f32 " \
                 "{%0,%1,%2,%3}, {%4,%5,%6,%7}, {%8,%9}, {%0,%1,%2,%3};" \
                 : "+f"((c)[0]), "+f"((c)[1]), "+f"((c)[2]), "+f"((c)[3]) \
                 : "r"(a0), "r"(a1), "r"(a2), "r"(a3), "r"(b0), "r"(b1))

// ---------------- pre-pass: x (fp32 NCHW) -> padded NHWC fp16 + per-(b,h) channel sums ----------------
__global__ __launch_bounds__(256)
void convert_x(const float* __restrict__ x)
{
    const int h = blockIdx.x, b = blockIdx.y, tid = threadIdx.x;
    __shared__ float t[64][65];
    for (int c0 = 0; c0 < 256; c0 += 64) {
        __syncthreads();
        for (int i = tid; i < 4096; i += 256) {
            int c = i >> 6, w = i & 63;
            t[c][w] = x[(((size_t)b * 256 + c0 + c) * 64 + h) * 64 + w];
        }
        __syncthreads();
        for (int i = tid; i < 4096; i += 256) {
            int w = i >> 6, c = i & 63;
            g_xp[((b * 66u + h + 1) * 66u + (w + 1)) * 256 + c0 + c] = __float2half_rn(t[c][w]);
        }
        if (tid < 64) {   // per-channel row sum (fp32)
            float s = 0.f;
            #pragma unroll 8
            for (int w = 0; w < 64; ++w) s += t[tid][w];
            g_xph[(b * 64 + h) * 256 + c0 + tid] = s;
        }
    }
}

// ---------------- pre-pass: all weight reorders in one launch ----------------
__global__ __launch_bounds__(256)
void prep_all(const float* __restrict__ w1, const float* __restrict__ w2,
              const float* __restrict__ wo)
{
    int idx = blockIdx.x * 256 + threadIdx.x;
    if (idx < 36 * 64 * 64) {
        int j  = idx & 63;
        int oc = (idx >> 6) & 63;
        int kc = idx >> 12;
        int t = kc >> 2, cq = kc & 3;
        int ch = cq * 64 + j, dy = t / 3, dx = t % 3;
        g_w1p[idx] = __float2half_rn(w1[((oc * 256 + ch) * 3 + dy) * 3 + dx]);
        return;
    }
    idx -= 36 * 64 * 64;
    if (idx < 9 * 64 * 64) {
        int j  = idx & 63;
        int oc = (idx >> 6) & 63;
        int t  = idx >> 12;
        g_w2p[idx] = __float2half_rn(w2[(oc * 64 + j) * 9 + t]);
        return;
    }
    idx -= 9 * 64 * 64;
    if (idx < 256 * 64) g_wop[idx] = __float2half_rn(wo[idx]);
}

// ---------------- mma.sync conv3x3 + BN + ReLU ----------------
// Tile: M=128 (2 output rows x 64 w), N=64 oc. 4 warps, each 32 rows x 64 oc.
// A-tile (input) staged once per 64-ch group via cp.async; B (weights) double-buffered per tap.
// For !FIRST, also emits deterministic per-channel partial pool sums (g_ep1).
template<int CIN, int NG, bool FIRST>
__global__ __launch_bounds__(128)
void conv_mma(const float* __restrict__ bias,
              const float* __restrict__ bng, const float* __restrict__ bnb,
              const float* __restrict__ bnm, const float* __restrict__ bnv)
{
    extern __shared__ __align__(128) char dsm[];
    __half* sIn  = (__half*)dsm;                    // 264*128 = 33792 B
    char*   sBm  = dsm + 264 * 128;                 // 2 * 8192 B
    float*  sScale = (float*)(dsm + 264 * 128 + 16384);
    float*  sShift = sScale + 64;

    const int tid  = threadIdx.x;
    const int wid  = tid >> 5;
    const int lane = tid & 31;
    const int h0 = blockIdx.x * 2;
    const int b  = blockIdx.y;
    const int m0 = wid * 32;

    const __half* __restrict__ xin = FIRST ? g_xp : g_xp2;
    const __half* __restrict__ wgt = FIRST ? g_w1p : g_w2p;

    if (tid < 64) {
        float inv = bng[tid] * rsqrtf(bnv[tid] + EPS);
        sScale[tid] = inv;
        sShift[tid] = bnb[tid] - bnm[tid] * inv + bias[tid] * inv;
    }

    const uint32_t sInb = smem_u32(sIn);
    const uint32_t sBb  = smem_u32(sBm);

    int rb[2];
    #pragma unroll
    for (int mt = 0; mt < 2; ++mt) {
        int m_r = m0 + mt * 16 + (lane & 15);
        rb[mt] = (m_r >> 6) * 66 + (m_r & 63);
    }
    const uint32_t u_hi  = (uint32_t)(lane >> 4);
    const uint32_t b_row = (uint32_t)(lane & 15);

    float acc[2][8][4];
    #pragma unroll
    for (int mt = 0; mt < 2; ++mt)
        #pragma unroll
        for (int j = 0; j < 8; ++j)
            #pragma unroll
            for (int q = 0; q < 4; ++q) acc[mt][j][q] = 0.f;

    for (int g = 0; g < NG; ++g) {
        if (g) __syncthreads();   // prior group's smem reads done
        const int ch0 = g * 64;
        // stage input tile: 264 rows x 8 units (cp.async)
        for (int i = tid; i < 264 * 8; i += 128) {
            int r = i >> 3, u = i & 7;
            int dyr = r / 66, wpos = r - dyr * 66;
            const __half* src = xin + ((size_t)((b * 66 + h0 + dyr) * 66 + wpos)) * CIN + ch0 + u * 8;
            CP_ASYNC16(sInb + swz((uint32_t)r, (uint32_t)u), src);
        }
        // stage B for tap 0
        {
            const int kci = FIRST ? g : 0;
            const __half* ws = wgt + (size_t)kci * 4096;
            #pragma unroll
            for (int q = 0; q < 4; ++q) {
                int i = q * 128 + tid, r = i >> 3, u = i & 7;
                CP_ASYNC16(sBb + swz((uint32_t)r, (uint32_t)u), ws + r * 64 + u * 8);
            }
        }
        CP_COMMIT();
        CP_WAIT0();
        __syncthreads();

        for (int t = 0; t < 9; ++t) {
            if (t) { CP_WAIT0(); __syncthreads(); }
            if (t < 8) {   // prefetch next tap's B into the other buffer
                const int kci = FIRST ? ((t + 1) * 4 + g) : (t + 1);
                const __half* ws = wgt + (size_t)kci * 4096;
                const uint32_t dstb = sBb + (uint32_t)(((t + 1) & 1) * 8192);
                #pragma unroll
                for (int q = 0; q < 4; ++q) {
                    int i = q * 128 + tid, r = i >> 3, u = i & 7;
                    CP_ASYNC16(dstb + swz((uint32_t)r, (uint32_t)u), ws + r * 64 + u * 8);
                }
                CP_COMMIT();
            }
            const int off = (t / 3) * 66 + (t % 3);
            const uint32_t bbase = sBb + (uint32_t)((t & 1) * 8192);
            #pragma unroll
            for (int s = 0; s < 4; ++s) {
                const uint32_t u = (uint32_t)(s * 2) + u_hi;
                uint32_t a[2][4];
                #pragma unroll
                for (int mt = 0; mt < 2; ++mt)
                    LDMATRIX_X4(a[mt][0], a[mt][1], a[mt][2], a[mt][3],
                                sInb + swz((uint32_t)(rb[mt] + off), u));
                uint32_t bf[4][4];
                #pragma unroll
                for (int nt = 0; nt < 4; ++nt)
                    LDMATRIX_X4(bf[nt][0], bf[nt][1], bf[nt][2], bf[nt][3],
                                bbase + swz(b_row + nt * 16, u));
                #pragma unroll
                for (int mt = 0; mt < 2; ++mt)
                    #pragma unroll
                    for (int j = 0; j < 8; ++j) {
                        const int nt = j >> 1, lo = j & 1;
                        MMA_16816(acc[mt][j], a[mt][0], a[mt][1], a[mt][2], a[mt][3],
                                  bf[nt][lo], bf[nt][2 + lo]);
                    }
            }
        }
    }

    // ---------------- epilogue: BN + ReLU (+ pool partials for !FIRST) ----------------
    const int r0 = lane >> 2;
    const int c0 = (lane & 3) * 2;
    float ps[16];
    #pragma unroll
    for (int k = 0; k < 16; ++k) ps[k] = 0.f;

    #pragma unroll
    for (int mt = 0; mt < 2; ++mt) {
        #pragma unroll
        for (int half = 0; half < 2; ++half) {
            const int m = m0 + mt * 16 + r0 + half * 8;
            const int hh = m >> 6, w = m & 63;
            if (FIRST) {
                __half* dst = g_xp2 + ((size_t)((b * 66 + h0 + hh + 1) * 66) + (w + 1)) * 64;
                #pragma unroll
                for (int j = 0; j < 8; ++j) {
                    const int oc = j * 8 + c0;
                    float v0 = fmaxf(acc[mt][j][half * 2]     * sScale[oc]     + sShift[oc],     0.f);
                    float v1 = fmaxf(acc[mt][j][half * 2 + 1] * sScale[oc + 1] + sShift[oc + 1], 0.f);
                    *(half2*)(dst + oc) = __floats2half2_rn(v0, v1);
                }
            } else {
                __half* dst = g_ef + ((size_t)(b * 4096 + (h0 + hh) * 64 + w)) * 64;
                #pragma unroll
                for (int j = 0; j < 8; ++j) {
                    const int oc = j * 8 + c0;
                    float v0 = fmaxf(acc[mt][j][half * 2]     * sScale[oc]     + sShift[oc],     0.f);
                    float v1 = fmaxf(acc[mt][j][half * 2 + 1] * sScale[oc + 1] + sShift[oc + 1], 0.f);
                    half2 hv = __floats2half2_rn(v0, v1);
                    *(half2*)(dst + oc) = hv;
                    // pool accumulates the rounded fp16 values (matches g_ef contents)
                    float2 vr = __half22float2(hv);
                    ps[j * 2]     += vr.x;
                    ps[j * 2 + 1] += vr.y;
                }
            }
        }
    }

    if (!FIRST) {
        // deterministic reduce: shfl-xor over r0 (lanes sharing c0), then fold 4 warps via smem
        #pragma unroll
        for (int k = 0; k < 16; ++k) {
            #pragma unroll
            for (int off = 4; off < 32; off <<= 1)
                ps[k] += __shfl_xor_sync(0xFFFFFFFFu, ps[k], off);
        }
        __syncthreads();                 // all smem (MMA) use done; reuse sIn area
        float* spool = (float*)dsm;      // [4][64]
        if (lane < 4) {
            #pragma unroll
            for (int j = 0; j < 8; ++j) {
                spool[wid * 64 + j * 8 + c0]     = ps[j * 2];
                spool[wid * 64 + j * 8 + c0 + 1] = ps[j * 2 + 1];
            }
        }
        __syncthreads();
        if (tid < 64)
            g_ep1[(b * 32 + blockIdx.x) * 64 + tid] =
                (spool[tid] + spool[64 + tid]) + (spool[128 + tid] + spool[192 + tid]);
    }
}

// ---------------- fused gate: pools fold -> MLP1+BN+ReLU -> MLP2+sigmoid ----------------
__global__ __launch_bounds__(256)
void gate_fused(const float* __restrict__ g1_w, const float* __restrict__ g1_b,
                const float* __restrict__ gbng, const float* __restrict__ gbnb,
                const float* __restrict__ gbnm, const float* __restrict__ gbnv,
                const float* __restrict__ g2_w, const float* __restrict__ g2_b)
{
    const int b = blockIdx.x, t = threadIdx.x;
    __shared__ float gv[320];
    __shared__ float hv[128];

    for (int i = t; i < 320; i += 256) {
        float s = 0.f;
        if (i < 256) {
            #pragma unroll 8
            for (int h = 0; h < 64; ++h) s += g_xph[(b * 64 + h) * 256 + i];
        } else {
            const int c = i - 256;
            #pragma unroll 8
            for (int seg = 0; seg < 32; ++seg) s += g_ep1[(b * 32 + seg) * 64 + c];
        }
        gv[i] = s * (1.f / 4096.f);
    }
    __syncthreads();

    if (t < 128) {
        float s = g1_b[t];
        const float* wrow = g1_w + t * 320;
        #pragma unroll 4
        for (int k = 0; k < 320; ++k) s = fmaf(gv[k], wrow[k], s);
        float inv = gbng[t] * rsqrtf(gbnv[t] + EPS);
        s = (s - gbnm[t]) * inv + gbnb[t];
        hv[t] = fmaxf(s, 0.f);
    }
    __syncthreads();

    float s = g2_b[t];
    const float* wrow = g2_w + t * 128;
    #pragma unroll 4
    for (int k = 0; k < 128; ++k) s = fmaf(hv[k], wrow[k], s);
    g_gate[b * 256 + t] = 1.f / (1.f + expf(-s));
}

// ---------------- 1x1 conv (64->256) via HMMA + gated residual add ----------------
__global__ __launch_bounds__(256)
void out_mma(const float* __restrict__ x, const float* __restrict__ out_b,
             float* __restrict__ out)
{
    __shared__ __align__(128) __half sW[256 * 64];
    __shared__ __align__(128) __half sE[64 * 64];
    const int tid = threadIdx.x, wid = tid >> 5, lane = tid & 31;
    const int h = blockIdx.x, b = blockIdx.y;

    for (int i = tid; i < 2048; i += 256) {
        int r = i >> 3, u = i & 7;
        *(uint4*)((char*)sW + swz((uint32_t)r, (uint32_t)u)) = *(const uint4*)(g_wop + r * 64 + u * 8);
    }
    for (int i = tid; i < 512; i += 256) {
        int r = i >> 3, u = i & 7;
        *(uint4*)((char*)sE + swz((uint32_t)r, (uint32_t)u)) =
            *(const uint4*)(g_ef + ((size_t)(b * 4096 + h * 64 + r)) * 64 + u * 8);
    }
    __syncthreads();

    const int m0 = wid * 32;
    const uint32_t sWb = smem_u32(sW), sEb = smem_u32(sE);
    const uint32_t a_row = (uint32_t)(m0 + (lane & 15));
    const uint32_t b_row = (uint32_t)(lane & 15);
    const uint32_t u_hi  = (uint32_t)(lane >> 4);

    float acc[2][8][4];
    #pragma unroll
    for (int mt = 0; mt < 2; ++mt)
        #pragma unroll
        for (int j = 0; j < 8; ++j)
            #pragma unroll
            for (int q = 0; q < 4; ++q) acc[mt][j][q] = 0.f;

    #pragma unroll
    for (int s = 0; s < 4; ++s) {
        const uint32_t u = (uint32_t)(s * 2) + u_hi;
        uint32_t a[2][4];
        #pragma unroll
        for (int mt = 0; mt < 2; ++mt)
            LDMATRIX_X4(a[mt][0], a[mt][1], a[mt][2], a[mt][3], sWb + swz(a_row + mt * 16, u));
        uint32_t bf[4][4];
        #pragma unroll
        for (int nt = 0; nt < 4; ++nt)
            LDMATRIX_X4(bf[nt][0], bf[nt][1], bf[nt][2], bf[nt][3], sEb + swz(b_row + nt * 16, u));
        #pragma unroll
        for (int mt = 0; mt < 2; ++mt)
            #pragma unroll
            for (int j = 0; j < 8; ++j) {
                const int nt = j >> 1, lo = j & 1;
                MMA_16816(acc[mt][j], a[mt][0], a[mt][1], a[mt][2], a[mt][3],
                          bf[nt][lo], bf[nt][2 + lo]);
            }
    }

    const int r0 = lane >> 2, c0 = (lane & 3) * 2;
    #pragma unroll
    for (int mt = 0; mt < 2; ++mt) {
        #pragma unroll
        for (int half = 0; half < 2; ++half) {
            const int oc = m0 + mt * 16 + r0 + half * 8;
            const float gt = g_gate[b * 256 + oc];
            const float bia = out_b[oc];
            const size_t base = ((size_t)(b * 256 + oc) * 64 + h) * 64;
            #pragma unroll
            for (int j = 0; j < 8; ++j) {
                const int w = j * 8 + c0;
                float2 xv = *(const float2*)&x[base + w];
                float2 o;
                o.x = xv.x + gt * (acc[mt][j][half * 2]     + bia);
                o.y = xv.y + gt * (acc[mt][j][half * 2 + 1] + bia);
                *(float2*)&out[base + w] = o;
            }
        }
    }
}

// ---------------- launch ----------------
extern "C" void kernel_launch(void* const* d_in, const int* in_sizes, int n_in,
                              void* d_out, int out_size)
{
    const float* x     = (const float*)d_in[0];
    const float* ec1_w = (const float*)d_in[1];
    const float* ec1_b = (const float*)d_in[2];
    const float* bn1_g = (const float*)d_in[3];
    const float* bn1_b = (const float*)d_in[4];
    const float* bn1_m = (const float*)d_in[5];
    const float* bn1_v = (const float*)d_in[6];
    const float* ec2_w = (const float*)d_in[7];
    const float* ec2_b = (const float*)d_in[8];
    const float* bn2_g = (const float*)d_in[9];
    const float* bn2_b = (const float*)d_in[10];
    const float* bn2_m = (const float*)d_in[11];
    const float* bn2_v = (const float*)d_in[12];
    const float* g1_w  = (const float*)d_in[13];
    const float* g1_b  = (const float*)d_in[14];
    const float* gbn_g = (const float*)d_in[15];
    const float* gbn_b = (const float*)d_in[16];
    const float* gbn_m = (const float*)d_in[17];
    const float* gbn_v = (const float*)d_in[18];
    const float* g2_w  = (const float*)d_in[19];
    const float* g2_b  = (const float*)d_in[20];
    const float* out_w = (const float*)d_in[21];
    const float* out_b = (const float*)d_in[22];
    float* out = (float*)d_out;

    const int CONV_SMEM = 264 * 128 + 2 * 8192 + 2 * 64 * (int)sizeof(float);  // 50688
    cudaFuncSetAttribute(conv_mma<256, 4, true >, cudaFuncAttributeMaxDynamicSharedMemorySize, CONV_SMEM);
    cudaFuncSetAttribute(conv_mma< 64, 1, false>, cudaFuncAttributeMaxDynamicSharedMemorySize, CONV_SMEM);

    convert_x<<<dim3(64, 16), 256>>>(x);
    prep_all<<<784, 256>>>(ec1_w, ec2_w, out_w);

    conv_mma<256, 4, true ><<<dim3(32, 16), 128, CONV_SMEM>>>(ec1_b, bn1_g, bn1_b, bn1_m, bn1_v);
    conv_mma< 64, 1, false><<<dim3(32, 16), 128, CONV_SMEM>>>(ec2_b, bn2_g, bn2_b, bn2_m, bn2_v);

    gate_fused<<<16, 256>>>(g1_w, g1_b, gbn_g, gbn_b, gbn_m, gbn_v, g2_w, g2_b);
    out_mma<<<dim3(64, 16), 256>>>(x, out_b, out);
}